// round 12
// baseline (speedup 1.0000x reference)
#include <cuda_runtime.h>
#include <cuda_fp16.h>
#include <stdint.h>

#define NN 100000
#define NE 800000
#define C  100
#define OC 50
#define NBLK ((NN + 1023) / 1024)

#define TM 128
#define NTILES ((NN + TM - 1) / TM)
#define GEMM_GRID 296            // 2 CTAs per SM
#define GEMM_THREADS 256

// word stride per row: reads touch words 0..55; WS=60 -> conflict-free frags
#define WS 60
#define SA 0
#define SB (TM * WS)                   // 7680
#define SM_WORDS (SB + 104 * WS)       // 13920 words = 55680 B (2 CTAs/SM)

// ---------------- device globals (scratch; zero-init at load) ----------------
__device__ __align__(16) float d_dis[NN];
__device__ __align__(16) __half d_G16[NN * C];
__device__ __align__(16) __half d_H16[NN * C];
__device__ int d_cnt[NN];      // re-zeroed at tail of gather mode 1 each run
__device__ int d_start[NN];    // after k_fill: END pointers
__device__ int d_csr[NE];
__device__ int d_bsum[NBLK + 1];

// ---------------- mma helper (baseline PTX, sm_80+) ----------------
__device__ __forceinline__ void mma_f16(float* d, const uint32_t* a, const uint32_t* b) {
    asm volatile(
        "mma.sync.aligned.m16n8k16.row.col.f32.f16.f16.f32 "
        "{%0,%1,%2,%3}, {%4,%5,%6,%7}, {%8,%9}, {%0,%1,%2,%3};"
        : "+f"(d[0]), "+f"(d[1]), "+f"(d[2]), "+f"(d[3])
        : "r"(a[0]), "r"(a[1]), "r"(a[2]), "r"(a[3]), "r"(b[0]), "r"(b[1]));
}

// ---------------- CSR build (deg fused into GEMM1) ----------------
__global__ void k_scan1() {   // block-local exclusive scan + dis = rsqrt(cnt+1)
    __shared__ int sh[1024];
    int i = blockIdx.x * 1024 + threadIdx.x;
    int v = (i < NN) ? d_cnt[i] : 0;
    sh[threadIdx.x] = v;
    __syncthreads();
    for (int off = 1; off < 1024; off <<= 1) {
        int t = (threadIdx.x >= off) ? sh[threadIdx.x - off] : 0;
        __syncthreads();
        sh[threadIdx.x] += t;
        __syncthreads();
    }
    if (i < NN) {
        d_start[i] = sh[threadIdx.x] - v;
        d_dis[i] = rsqrtf((float)v + 1.0f);
    }
    if (threadIdx.x == 1023) d_bsum[blockIdx.x] = sh[1023];
}
__global__ void k_scan23() {   // every block redundantly scans the 98 partials
    __shared__ int sh[128];
    int t = threadIdx.x;
    sh[t] = (t < NBLK) ? d_bsum[t] : 0;
    __syncthreads();
    for (int off = 1; off < 128; off <<= 1) {
        int u = (t >= off) ? sh[t - off] : 0;
        __syncthreads();
        sh[t] += u;
        __syncthreads();
    }
    for (int q = 0; q < 2; q++) {
        int idx = blockIdx.x * 256 + q * 128 + t;
        if (idx < NN) {
            int blk = idx >> 10;
            int boff = (blk > 0) ? sh[blk - 1] : 0;
            d_start[idx] += boff;
        }
    }
}
__global__ void k_fill(const int* __restrict__ src, const int* __restrict__ dst) {
    int e = blockIdx.x * blockDim.x + threadIdx.x;
    if (e >= NE) return;
    int d = dst[e];
    int p = atomicAdd(&d_start[d], 1);   // start[] becomes END pointers
    d_csr[p] = src[e];
}

// ---------------- single-pass fp16 GEMM, reg-prefetch pipelined ----------------
// mode 0: A = x fp32 -> fp16; W = W0; do_deg=1; NO dis scaling (dis not ready)
// mode 1: A = d_H16 fp16;     W = [Wa | Wb]; scaled by dis[row]
__device__ __forceinline__ void load_rows(int t, uint2* pre, int mode,
                                          const float* __restrict__ Ain, int tid) {
    const int i0 = t * TM;
    const int rowlim = NN - i0;
    #pragma unroll
    for (int it = 0; it < 13; it++) {
        int q = it * 256 + tid;
        uint2 w2 = make_uint2(0u, 0u);
        if (q < TM * 25) {
            int r = q / 25, c4 = (q % 25) * 4;
            if (r < rowlim) {
                if (mode == 0) {
                    float4 v = *(const float4*)&Ain[(size_t)(i0 + r) * C + c4];
                    __half2 h0 = __floats2half2_rn(v.x, v.y);
                    __half2 h1 = __floats2half2_rn(v.z, v.w);
                    w2.x = *reinterpret_cast<uint32_t*>(&h0);
                    w2.y = *reinterpret_cast<uint32_t*>(&h1);
                } else {
                    w2 = *(const uint2*)&d_H16[(size_t)(i0 + r) * C + c4];
                }
            }
        }
        pre[it] = w2;
    }
}

__global__ void __launch_bounds__(GEMM_THREADS, 2)
k_gemm(const float* __restrict__ Ain, const float* __restrict__ W0,
       const float* __restrict__ Wa, const float* __restrict__ Wb,
       int mode, int do_deg, const int* __restrict__ dst) {
    extern __shared__ uint32_t sm[];
    const int tid = threadIdx.x, wid = tid >> 5, lane = tid & 31;
    const int g = lane >> 2, tg = lane & 3;

    // fused degree count (mode 0 only): fire-and-forget REDGs drain during MMA
    if (do_deg) {
        for (int e = blockIdx.x * GEMM_THREADS + tid; e < NE;
             e += GEMM_GRID * GEMM_THREADS)
            atomicAdd(&d_cnt[dst[e]], 1);
    }

    for (int i = tid; i < SM_WORDS; i += GEMM_THREADS) sm[i] = 0;
    __syncthreads();

    // stage W -> fp16; layout B[n][kword]
    for (int idx = tid; idx < C * C; idx += GEMM_THREADS) {
        int k = idx / C, n = idx % C;
        float w = (mode == 0) ? W0[idx]
                              : ((n < OC) ? Wa[k * OC + n] : Wb[k * OC + (n - OC)]);
        ((__half*)(sm + SB))[(n * WS + (k >> 1)) * 2 + (k & 1)] = __float2half_rn(w);
    }

    const int r0 = wid * 16;   // 8 warps x 16 rows = 128
    const int stride = GEMM_GRID;

    uint2 pre[13];
    int t = blockIdx.x;
    if (t < NTILES) load_rows(t, pre, mode, Ain, tid);
    __syncthreads();   // W staged (A-prefetch is in regs, not smem)

    for (; t < NTILES; t += stride) {
        // store prefetched A tile -> smem
        #pragma unroll
        for (int it = 0; it < 13; it++) {
            int q = it * 256 + tid;
            if (q < TM * 25) {
                int r = q / 25, c4 = (q % 25) * 4;
                *(uint2*)(sm + SA + r * WS + (c4 >> 1)) = pre[it];
            }
        }
        __syncthreads();

        // issue next tile's loads while current tile computes
        int tn = t + stride;
        if (tn < NTILES) load_rows(tn, pre, mode, Ain, tid);

        float acc[13][4];
        #pragma unroll
        for (int nt = 0; nt < 13; nt++)
            #pragma unroll
            for (int q = 0; q < 4; q++) acc[nt][q] = 0.f;

        #pragma unroll
        for (int kt = 0; kt < 7; kt++) {
            const int kw = kt * 8;
            uint32_t a[4];
            a[0] = sm[SA + (r0 + g) * WS + kw + tg];
            a[1] = sm[SA + (r0 + g + 8) * WS + kw + tg];
            a[2] = sm[SA + (r0 + g) * WS + kw + 4 + tg];
            a[3] = sm[SA + (r0 + g + 8) * WS + kw + 4 + tg];
            #pragma unroll
            for (int nt = 0; nt < 13; nt++) {
                const int n0 = nt * 8;
                uint32_t b[2];
                b[0] = sm[SB + (n0 + g) * WS + kw + tg];
                b[1] = sm[SB + (n0 + g) * WS + kw + 4 + tg];
                mma_f16(acc[nt], a, b);
            }
        }

        const int i0 = t * TM;
        const int row1 = i0 + r0 + g, row2 = row1 + 8;
        // mode 0: store UNSCALED (d_dis not computed yet); mode 1: scale by dis
        const float s1 = (row1 < NN) ? ((mode == 0) ? 1.0f : d_dis[row1]) : 0.f;
        const float s2 = (row2 < NN) ? ((mode == 0) ? 1.0f : d_dis[row2]) : 0.f;
        #pragma unroll
        for (int nt = 0; nt < 13; nt++) {
            const int c = nt * 8 + 2 * tg;
            if (c < C) {
                if (row1 < NN)
                    *(__half2*)&d_G16[(size_t)row1 * C + c] =
                        __floats2half2_rn(s1 * acc[nt][0], s1 * acc[nt][1]);
                if (row2 < NN)
                    *(__half2*)&d_G16[(size_t)row2 * C + c] =
                        __floats2half2_rn(s2 * acc[nt][2], s2 * acc[nt][3]);
            }
        }
        __syncthreads();   // all smem reads done before next store phase
    }
}

// ---------------- gather + epilogues ----------------
__device__ __forceinline__ float4 ldg_h4(const __half* p) {
    uint2 r = *(const uint2*)p;
    __half2 a = *reinterpret_cast<__half2*>(&r.x);
    __half2 b = *reinterpret_cast<__half2*>(&r.y);
    float2 f0 = __half22float2(a), f1 = __half22float2(b);
    return make_float4(f0.x, f0.y, f1.x, f1.y);
}

// mode 0 (G unscaled): h = relu(dis[w]*(sum_e dis[s]*G[s] + dis[w]*G[w]) + b1)
// mode 1 (G scaled):   out = dis[w]*(G[w] + sum_e G[s]) + bias, split mu/ls
__global__ void k_gather(int mode, const float* __restrict__ b1,
                         const float* __restrict__ bmu, const float* __restrict__ bls,
                         float* __restrict__ out) {
    int w = (blockIdx.x * blockDim.x + threadIdx.x) >> 5;
    int lane = threadIdx.x & 31;
    if (w >= NN || lane >= 25) return;
    int en = d_start[w];
    int n  = d_cnt[w];
    if (mode == 1 && lane == 0) d_cnt[w] = 0;   // reset for next run (post-read)
    int st = en - n;
    int p4 = lane * 4;
    float sc = d_dis[w];

    float4 self = ldg_h4(&d_G16[(size_t)w * C + p4]);
    float4 acc;

    if (mode == 0) {
        // self-loop term scaled by dis[w]
        acc = make_float4(sc * self.x, sc * self.y, sc * self.z, sc * self.w);
        for (int j = 0; j < n; j++) {
            int s = d_csr[st + j];
            float ds = d_dis[s];                 // lane-uniform -> broadcast
            float4 v = ldg_h4(&d_G16[(size_t)s * C + p4]);
            acc.x = fmaf(ds, v.x, acc.x);
            acc.y = fmaf(ds, v.y, acc.y);
            acc.z = fmaf(ds, v.z, acc.z);
            acc.w = fmaf(ds, v.w, acc.w);
        }
        float4 bb = *(const float4*)&b1[p4];
        __half2 h0 = __floats2half2_rn(fmaxf(fmaf(sc, acc.x, bb.x), 0.f),
                                       fmaxf(fmaf(sc, acc.y, bb.y), 0.f));
        __half2 h1 = __floats2half2_rn(fmaxf(fmaf(sc, acc.z, bb.z), 0.f),
                                       fmaxf(fmaf(sc, acc.w, bb.w), 0.f));
        uint2 packed;
        packed.x = *reinterpret_cast<uint32_t*>(&h0);
        packed.y = *reinterpret_cast<uint32_t*>(&h1);
        *(uint2*)&d_H16[(size_t)w * C + p4] = packed;
    } else {
        acc = self;
        for (int j = 0; j < n; j++) {
            int s = d_csr[st + j];
            float4 v = ldg_h4(&d_G16[(size_t)s * C + p4]);
            acc.x += v.x; acc.y += v.y; acc.z += v.z; acc.w += v.w;
        }
        float v[4] = { sc * acc.x, sc * acc.y, sc * acc.z, sc * acc.w };
        #pragma unroll
        for (int q = 0; q < 4; q++) {
            int c = p4 + q;
            if (c < OC) out[(size_t)w * OC + c]                          = v[q] + bmu[c];
            else        out[(size_t)NN * OC + (size_t)w * OC + (c - OC)] = v[q] + bls[c - OC];
        }
    }
}

extern "C" void kernel_launch(void* const* d_in, const int* in_sizes, int n_in,
                              void* d_out, int out_size) {
    const float* x   = (const float*)d_in[0];
    const int*   ei  = (const int*)  d_in[1];
    const float* W1  = (const float*)d_in[2];
    const float* b1  = (const float*)d_in[3];
    const float* Wmu = (const float*)d_in[4];
    const float* bmu = (const float*)d_in[5];
    const float* Wls = (const float*)d_in[6];
    const float* bls = (const float*)d_in[7];
    float* out = (float*)d_out;

    const int* src = ei;
    const int* dst = ei + NE;

    cudaFuncSetAttribute(k_gemm, cudaFuncAttributeMaxDynamicSharedMemorySize, SM_WORDS * 4);

    // GEMM1 (unscaled G) with fused degree counting; dis NOT read here
    k_gemm<<<GEMM_GRID, GEMM_THREADS, SM_WORDS * 4>>>(x, W1, nullptr, nullptr, 0, 1, dst);

    // CSR finish (computes d_dis too)
    k_scan1<<<NBLK, 1024>>>();
    k_scan23<<<(NN + 255) / 256, 128>>>();
    k_fill<<<(NE + 255) / 256, 256>>>(src, dst);

    // layer 1 aggregate (applies dis[s] per edge + dis[w])
    k_gather<<<(NN * 32 + 255) / 256, 256>>>(0, b1, nullptr, nullptr, nullptr);

    // layers 2+3 fused (mu | logstd column-concat), G scaled by dis[row]
    k_gemm<<<GEMM_GRID, GEMM_THREADS, SM_WORDS * 4>>>(nullptr, nullptr, Wmu, Wls, 1, 0, nullptr);
    k_gather<<<(NN * 32 + 255) / 256, 256>>>(1, nullptr, bmu, bls, out);
}

// round 13
// speedup vs baseline: 2.0464x; 2.0464x over previous
#include <cuda_runtime.h>
#include <cuda_fp16.h>
#include <stdint.h>

#define NN 100000
#define NE 800000
#define C  100
#define OC 50
#define NBLK ((NN + 1023) / 1024)

#define TM 128
#define NTILES ((NN + TM - 1) / TM)
#define GEMM_GRID 296            // 2 CTAs per SM
#define GEMM_THREADS 256

// word stride per row: reads touch words 0..55; WS=60 -> conflict-free frags
#define WS 60
#define SA0 0
#define SA1 (TM * WS)                  // 7680
#define SB  (2 * TM * WS)              // 15360
#define SM_WORDS (SB + 104 * WS)       // 21600 words = 86400 B (2 CTAs/SM)

#define CVT_QUADS (NN * 25)

// ---------------- device globals (scratch; zero-init at load) ----------------
__device__ __align__(16) float d_dis[NN];
__device__ __align__(16) __half d_X16[NN * C];   // x pre-converted to fp16
__device__ __align__(16) __half d_G16[NN * C];
__device__ __align__(16) __half d_H16[NN * C];
__device__ int d_cnt[NN];      // re-zeroed at tail of gather mode 1 each run
__device__ int d_start[NN];    // after k_fill: END pointers
__device__ int d_csr[NE];
__device__ int d_bsum[NBLK + 1];

// ---------------- PTX helpers (baseline, sm_80+) ----------------
__device__ __forceinline__ void mma_f16(float* d, const uint32_t* a, const uint32_t* b) {
    asm volatile(
        "mma.sync.aligned.m16n8k16.row.col.f32.f16.f16.f32 "
        "{%0,%1,%2,%3}, {%4,%5,%6,%7}, {%8,%9}, {%0,%1,%2,%3};"
        : "+f"(d[0]), "+f"(d[1]), "+f"(d[2]), "+f"(d[3])
        : "r"(a[0]), "r"(a[1]), "r"(a[2]), "r"(a[3]), "r"(b[0]), "r"(b[1]));
}
__device__ __forceinline__ void cp_async8(uint32_t saddr, const void* g, int src_sz) {
    asm volatile("cp.async.ca.shared.global [%0], [%1], 8, %2;"
                 :: "r"(saddr), "l"(g), "r"(src_sz));
}
#define CP_COMMIT() asm volatile("cp.async.commit_group;" ::: "memory")
#define CP_WAIT1()  asm volatile("cp.async.wait_group 1;" ::: "memory")

// ---------------- CSR build + x conversion ----------------
__global__ void k_degcvt(const int* __restrict__ dst, const float* __restrict__ x) {
    int i = blockIdx.x * blockDim.x + threadIdx.x;
    if (i < NE) atomicAdd(&d_cnt[dst[i]], 1);    // cnt pre-zeroed
    if (i < CVT_QUADS) {
        int r = i / 25, c4 = (i % 25) * 4;
        float4 v = *(const float4*)&x[(size_t)r * C + c4];
        __half2 h0 = __floats2half2_rn(v.x, v.y);
        __half2 h1 = __floats2half2_rn(v.z, v.w);
        uint2 w2;
        w2.x = *reinterpret_cast<uint32_t*>(&h0);
        w2.y = *reinterpret_cast<uint32_t*>(&h1);
        *(uint2*)&d_X16[(size_t)r * C + c4] = w2;
    }
}
__global__ void k_scan1() {   // block-local exclusive scan + dis = rsqrt(cnt+1)
    __shared__ int sh[1024];
    int i = blockIdx.x * 1024 + threadIdx.x;
    int v = (i < NN) ? d_cnt[i] : 0;
    sh[threadIdx.x] = v;
    __syncthreads();
    for (int off = 1; off < 1024; off <<= 1) {
        int t = (threadIdx.x >= off) ? sh[threadIdx.x - off] : 0;
        __syncthreads();
        sh[threadIdx.x] += t;
        __syncthreads();
    }
    if (i < NN) {
        d_start[i] = sh[threadIdx.x] - v;
        d_dis[i] = rsqrtf((float)v + 1.0f);
    }
    if (threadIdx.x == 1023) d_bsum[blockIdx.x] = sh[1023];
}
__global__ void k_scan23() {   // every block redundantly scans the 98 partials
    __shared__ int sh[128];
    int t = threadIdx.x;
    sh[t] = (t < NBLK) ? d_bsum[t] : 0;
    __syncthreads();
    for (int off = 1; off < 128; off <<= 1) {
        int u = (t >= off) ? sh[t - off] : 0;
        __syncthreads();
        sh[t] += u;
        __syncthreads();
    }
    for (int q = 0; q < 2; q++) {
        int idx = blockIdx.x * 256 + q * 128 + t;
        if (idx < NN) {
            int blk = idx >> 10;
            int boff = (blk > 0) ? sh[blk - 1] : 0;
            d_start[idx] += boff;
        }
    }
}
__global__ void k_fill(const int* __restrict__ src, const int* __restrict__ dst) {
    int e = blockIdx.x * blockDim.x + threadIdx.x;
    if (e >= NE) return;
    int d = dst[e];
    int p = atomicAdd(&d_start[d], 1);   // start[] becomes END pointers
    d_csr[p] = src[e];
}

// ---------------- fp16 GEMM, cp.async double-buffered ----------------
// G16 = dis[row] * (A @ W); A always fp16 (d_X16 or d_H16)
// mode 0: W = W0 [C x C]; mode 1: W = [Wa | Wb] column-concat
__device__ __forceinline__ void issue_tile(int t, const __half* __restrict__ A,
                                           uint32_t sa_u32, int tid) {
    const int i0 = t * TM;
    const int rowlim = NN - i0;
    #pragma unroll
    for (int it = 0; it < 13; it++) {
        int q = it * 256 + tid;
        if (q < TM * 25) {
            int r = q / 25, c4 = (q % 25) * 4;
            int ok = (r < rowlim);
            const __half* src = &A[(size_t)(i0 + (ok ? r : 0)) * C + c4];
            cp_async8(sa_u32 + (uint32_t)(r * WS + (c4 >> 1)) * 4, src, ok ? 8 : 0);
        }
    }
}

__global__ void __launch_bounds__(GEMM_THREADS, 2)
k_gemm(const __half* __restrict__ A, const float* __restrict__ W0,
       const float* __restrict__ Wa, const float* __restrict__ Wb, int mode) {
    extern __shared__ uint32_t sm[];
    const int tid = threadIdx.x, wid = tid >> 5, lane = tid & 31;
    const int g = lane >> 2, tg = lane & 3;
    const uint32_t smb = (uint32_t)__cvta_generic_to_shared(sm);

    for (int i = tid; i < SM_WORDS; i += GEMM_THREADS) sm[i] = 0;
    __syncthreads();   // zero done before any cp.async writes

    // stage W -> fp16; layout B[n][kword]
    for (int idx = tid; idx < C * C; idx += GEMM_THREADS) {
        int k = idx / C, n = idx % C;
        float w = (mode == 0) ? W0[idx]
                              : ((n < OC) ? Wa[k * OC + n] : Wb[k * OC + (n - OC)]);
        ((__half*)(sm + SB))[(n * WS + (k >> 1)) * 2 + (k & 1)] = __float2half_rn(w);
    }

    const int r0 = wid * 16;   // 8 warps x 16 rows = 128
    const int stride = GEMM_GRID;
    int t = blockIdx.x;
    int buf = 0;               // buffer holding tile t
    if (t < NTILES) issue_tile(t, A, smb + SA0 * 4, tid);
    CP_COMMIT();

    for (; t < NTILES; t += stride) {
        int tn = t + stride;
        if (tn < NTILES)
            issue_tile(tn, A, smb + (buf ? SA0 : SA1) * 4, tid);
        CP_COMMIT();
        CP_WAIT1();            // oldest group (tile t) complete
        __syncthreads();       // also covers W staging on first iteration

        const uint32_t* sa = sm + (buf ? SA1 : SA0);

        float acc[13][4];
        #pragma unroll
        for (int nt = 0; nt < 13; nt++)
            #pragma unroll
            for (int q = 0; q < 4; q++) acc[nt][q] = 0.f;

        #pragma unroll
        for (int kt = 0; kt < 7; kt++) {
            const int kw = kt * 8;
            uint32_t a[4];
            a[0] = sa[(r0 + g) * WS + kw + tg];
            a[1] = sa[(r0 + g + 8) * WS + kw + tg];
            a[2] = sa[(r0 + g) * WS + kw + 4 + tg];
            a[3] = sa[(r0 + g + 8) * WS + kw + 4 + tg];
            #pragma unroll
            for (int nt = 0; nt < 13; nt++) {
                const int n0 = nt * 8;
                uint32_t b[2];
                b[0] = sm[SB + (n0 + g) * WS + kw + tg];
                b[1] = sm[SB + (n0 + g) * WS + kw + 4 + tg];
                mma_f16(acc[nt], a, b);
            }
        }

        const int i0 = t * TM;
        const int row1 = i0 + r0 + g, row2 = row1 + 8;
        const float s1 = (row1 < NN) ? d_dis[row1] : 0.f;
        const float s2 = (row2 < NN) ? d_dis[row2] : 0.f;
        #pragma unroll
        for (int nt = 0; nt < 13; nt++) {
            const int c = nt * 8 + 2 * tg;
            if (c < C) {
                if (row1 < NN)
                    *(__half2*)&d_G16[(size_t)row1 * C + c] =
                        __floats2half2_rn(s1 * acc[nt][0], s1 * acc[nt][1]);
                if (row2 < NN)
                    *(__half2*)&d_G16[(size_t)row2 * C + c] =
                        __floats2half2_rn(s2 * acc[nt][2], s2 * acc[nt][3]);
            }
        }
        __syncthreads();   // smem reads done before this buffer is refilled
        buf ^= 1;
    }
}

// ---------------- gather + epilogues (round-10 verbatim) ----------------
__device__ __forceinline__ float4 ldg_h4(const __half* p) {
    uint2 r = *(const uint2*)p;
    __half2 a = *reinterpret_cast<__half2*>(&r.x);
    __half2 b = *reinterpret_cast<__half2*>(&r.y);
    float2 f0 = __half22float2(a), f1 = __half22float2(b);
    return make_float4(f0.x, f0.y, f1.x, f1.y);
}

__global__ void k_gather(int mode, const float* __restrict__ b1,
                         const float* __restrict__ bmu, const float* __restrict__ bls,
                         float* __restrict__ out) {
    int w = (blockIdx.x * blockDim.x + threadIdx.x) >> 5;
    int lane = threadIdx.x & 31;
    if (w >= NN || lane >= 25) return;
    int en = d_start[w];
    int n  = d_cnt[w];
    if (mode == 1 && lane == 0) d_cnt[w] = 0;   // reset for next run (post-read)
    int st = en - n;
    int p4 = lane * 4;

    float4 acc = ldg_h4(&d_G16[(size_t)w * C + p4]);   // self-loop term
    for (int j = 0; j < n; j++) {
        int s = d_csr[st + j];
        float4 v = ldg_h4(&d_G16[(size_t)s * C + p4]);
        acc.x += v.x; acc.y += v.y; acc.z += v.z; acc.w += v.w;
    }
    float sc = d_dis[w];

    if (mode == 0) {
        float4 bb = *(const float4*)&b1[p4];
        __half2 h0 = __floats2half2_rn(fmaxf(fmaf(sc, acc.x, bb.x), 0.f),
                                       fmaxf(fmaf(sc, acc.y, bb.y), 0.f));
        __half2 h1 = __floats2half2_rn(fmaxf(fmaf(sc, acc.z, bb.z), 0.f),
                                       fmaxf(fmaf(sc, acc.w, bb.w), 0.f));
        uint2 packed;
        packed.x = *reinterpret_cast<uint32_t*>(&h0);
        packed.y = *reinterpret_cast<uint32_t*>(&h1);
        *(uint2*)&d_H16[(size_t)w * C + p4] = packed;
    } else {
        float v[4] = { sc * acc.x, sc * acc.y, sc * acc.z, sc * acc.w };
        #pragma unroll
        for (int q = 0; q < 4; q++) {
            int c = p4 + q;
            if (c < OC) out[(size_t)w * OC + c]                          = v[q] + bmu[c];
            else        out[(size_t)NN * OC + (size_t)w * OC + (c - OC)] = v[q] + bls[c - OC];
        }
    }
}

extern "C" void kernel_launch(void* const* d_in, const int* in_sizes, int n_in,
                              void* d_out, int out_size) {
    const float* x   = (const float*)d_in[0];
    const int*   ei  = (const int*)  d_in[1];
    const float* W1  = (const float*)d_in[2];
    const float* b1  = (const float*)d_in[3];
    const float* Wmu = (const float*)d_in[4];
    const float* bmu = (const float*)d_in[5];
    const float* Wls = (const float*)d_in[6];
    const float* bls = (const float*)d_in[7];
    float* out = (float*)d_out;

    const int* src = ei;
    const int* dst = ei + NE;

    // pointers to device globals for k_gemm's A argument
    __half* x16_ptr;  cudaGetSymbolAddress((void**)&x16_ptr, d_X16);
    __half* h16_ptr;  cudaGetSymbolAddress((void**)&h16_ptr, d_H16);

    cudaFuncSetAttribute(k_gemm, cudaFuncAttributeMaxDynamicSharedMemorySize, SM_WORDS * 4);

    // CSR build + x->fp16 conversion (fused; d_cnt arrives zeroed)
    k_degcvt<<<(CVT_QUADS + 255) / 256, 256>>>(dst, x);
    k_scan1<<<NBLK, 1024>>>();
    k_scan23<<<(NN + 255) / 256, 128>>>();
    k_fill<<<(NE + 255) / 256, 256>>>(src, dst);

    // layer 1
    k_gemm<<<GEMM_GRID, GEMM_THREADS, SM_WORDS * 4>>>(x16_ptr, W1, nullptr, nullptr, 0);
    k_gather<<<(NN * 32 + 255) / 256, 256>>>(0, b1, nullptr, nullptr, nullptr);

    // layers 2+3 fused (mu | logstd column-concat)
    k_gemm<<<GEMM_GRID, GEMM_THREADS, SM_WORDS * 4>>>(h16_ptr, nullptr, Wmu, Wls, 1);
    k_gather<<<(NN * 32 + 255) / 256, 256>>>(1, nullptr, bmu, bls, out);
}